// round 11
// baseline (speedup 1.0000x reference)
#include <cuda_runtime.h>

// SpikingLayer: input (B*T, 32*32*32) f32, B=16, T=128.
// Per (b, feat): state = max(syn_t + state - act, -1); act = s>0 ? floor(s) : 0.
//
// Pure HBM stream: 268MB in + 268MB out; DRAM-turnaround plateau ~6.1 TB/s.
// R10 probe: Blackwell 256-bit global accesses (ld/st.global.v8.f32).
// One thread = 8 features -> each warp load is a contiguous 1KB transaction,
// halving LDG/STG instruction count and per-request overhead vs float4.
// Retains all measured-best ingredients: 4-deep software-pipelined prefetch,
// .cs streaming loads, .wt write-through stores (R9's best-bench config).

#define T_STEPS 128
#define FEAT    32768            // 32*32*32 floats per time step
#define F8      (FEAT / 8)       // 4096 float8 per time step
#define BATCH   16

struct F8v { float v[8]; };

__device__ __forceinline__ F8v ldcs8(const float* p) {
    F8v r;
    asm volatile("ld.global.cs.v8.f32 {%0,%1,%2,%3,%4,%5,%6,%7}, [%8];"
                 : "=f"(r.v[0]), "=f"(r.v[1]), "=f"(r.v[2]), "=f"(r.v[3]),
                   "=f"(r.v[4]), "=f"(r.v[5]), "=f"(r.v[6]), "=f"(r.v[7])
                 : "l"(p));
    return r;
}

__device__ __forceinline__ void stwt8(float* p, const F8v& r) {
    asm volatile("st.global.wt.v8.f32 [%0], {%1,%2,%3,%4,%5,%6,%7,%8};"
                 :: "l"(p),
                    "f"(r.v[0]), "f"(r.v[1]), "f"(r.v[2]), "f"(r.v[3]),
                    "f"(r.v[4]), "f"(r.v[5]), "f"(r.v[6]), "f"(r.v[7])
                 : "memory");
}

__global__ __launch_bounds__(128)
void spiking_layer_kernel(const float* __restrict__ x, float* __restrict__ out) {
    const unsigned tid = blockIdx.x * blockDim.x + threadIdx.x;  // 0 .. 65535
    const unsigned b = tid >> 12;        // / 4096
    const unsigned f = tid & (F8 - 1);   // % 4096

    const size_t base = (size_t)b * T_STEPS * FEAT + (size_t)f * 8;
    const float* __restrict__ in = x + base;
    float* __restrict__ o = out + base;

    float s[8], a[8];
    #pragma unroll
    for (int i = 0; i < 8; i++) { s[i] = 0.f; a[i] = 0.f; }

    #define STEP_STORE(c, t_idx)                                           \
    {                                                                      \
        F8v r;                                                             \
        _Pragma("unroll")                                                  \
        for (int i = 0; i < 8; i++) {                                      \
            s[i] = fmaxf(c.v[i] + s[i] - a[i], -1.0f);                     \
            a[i] = (s[i] > 0.f) ? floorf(s[i]) : 0.f;                      \
            r.v[i] = a[i];                                                 \
        }                                                                  \
        stwt8(o + (size_t)(t_idx) * FEAT, r);                              \
    }

    // Prologue: chunk 0 (t = 0..3)
    F8v c0 = ldcs8(in + 0 * (size_t)FEAT);
    F8v c1 = ldcs8(in + 1 * (size_t)FEAT);
    F8v c2 = ldcs8(in + 2 * (size_t)FEAT);
    F8v c3 = ldcs8(in + 3 * (size_t)FEAT);

    #pragma unroll 1
    for (int t = 0; t < T_STEPS - 4; t += 4) {
        // Prefetch next chunk first (4 x 32B loads in flight per thread)
        F8v n0 = ldcs8(in + (size_t)(t + 4) * FEAT);
        F8v n1 = ldcs8(in + (size_t)(t + 5) * FEAT);
        F8v n2 = ldcs8(in + (size_t)(t + 6) * FEAT);
        F8v n3 = ldcs8(in + (size_t)(t + 7) * FEAT);

        STEP_STORE(c0, t + 0);
        STEP_STORE(c1, t + 1);
        STEP_STORE(c2, t + 2);
        STEP_STORE(c3, t + 3);

        c0 = n0; c1 = n1; c2 = n2; c3 = n3;
    }

    // Epilogue: t = 124..127
    STEP_STORE(c0, T_STEPS - 4);
    STEP_STORE(c1, T_STEPS - 3);
    STEP_STORE(c2, T_STEPS - 2);
    STEP_STORE(c3, T_STEPS - 1);

    #undef STEP_STORE
}

extern "C" void kernel_launch(void* const* d_in, const int* in_sizes, int n_in,
                              void* d_out, int out_size) {
    const float* x = (const float*)d_in[0];
    float* o = (float*)d_out;
    const int total_threads = BATCH * F8;          // 65536
    spiking_layer_kernel<<<total_threads / 128, 128>>>(x, o);
}

// round 12
// speedup vs baseline: 1.0495x; 1.0495x over previous
#include <cuda_runtime.h>

// SpikingLayer: input (B*T, 32*32*32) f32, B=16, T=128.
// Per (b, feat): state = max(syn_t + state - act, -1); act = s>0 ? floor(s) : 0.
//
// FINAL KERNEL (R9 config). Pure HBM stream: 268MB in + 268MB out, pinned at
// the B300 mixed-R/W DRAM ceiling (~6.1 TB/s = 77% of 8TB/s spec, turnaround-
// limited). Verified invariant across 10 variants: CTA shape, pipeline depth
// (2/4/6), store batching, occupancy (20%/41%/81%), access width (64/128/256b),
// and store policy all leave the plateau untouched (78.5-81 us kernel). Both
// streams are compulsory: the scalar time recurrence is nonlinear (no scan
// reformulation) and the f32 output dtype is fixed.
//
// Config: 1024 CTAs x 128 threads, one thread per float4 column, 4-deep
// software-pipelined prefetch (8 LDG.128 in flight/thread), .cs streaming
// loads, .wt write-through stores (never re-read; avoids lazy-writeback
// interleave against demand reads at the DRAM banks).

#define T_STEPS 128
#define FEAT    32768            // 32*32*32
#define F4      (FEAT / 4)       // 8192 float4 per time step
#define BATCH   16

__global__ __launch_bounds__(128, 8)
void spiking_layer_kernel(const float4* __restrict__ x, float4* __restrict__ out) {
    const unsigned tid = blockIdx.x * blockDim.x + threadIdx.x;  // 0 .. 131071
    const unsigned b = tid >> 13;        // / 8192
    const unsigned f = tid & (F4 - 1);   // % 8192

    const size_t base = (size_t)b * T_STEPS * F4 + f;
    const float4* __restrict__ in = x + base;
    float4* __restrict__ o = out + base;

    float sx = 0.f, sy = 0.f, sz = 0.f, sw = 0.f;   // membrane state
    float ax = 0.f, ay = 0.f, az = 0.f, aw = 0.f;   // last activation

    #define STEP_STORE(v, t_idx)                                          \
        sx = fmaxf(v.x + sx - ax, -1.0f);                                 \
        sy = fmaxf(v.y + sy - ay, -1.0f);                                 \
        sz = fmaxf(v.z + sz - az, -1.0f);                                 \
        sw = fmaxf(v.w + sw - aw, -1.0f);                                 \
        ax = (sx > 0.f) ? floorf(sx) : 0.f;                               \
        ay = (sy > 0.f) ? floorf(sy) : 0.f;                               \
        az = (sz > 0.f) ? floorf(sz) : 0.f;                               \
        aw = (sw > 0.f) ? floorf(sw) : 0.f;                               \
        __stwt(o + (size_t)(t_idx) * F4, make_float4(ax, ay, az, aw));

    // Prologue: load chunk 0 (t = 0..3)
    float4 c0 = __ldcs(in + 0 * (size_t)F4);
    float4 c1 = __ldcs(in + 1 * (size_t)F4);
    float4 c2 = __ldcs(in + 2 * (size_t)F4);
    float4 c3 = __ldcs(in + 3 * (size_t)F4);

    #pragma unroll 1
    for (int t = 0; t < T_STEPS - 4; t += 4) {
        // Prefetch next chunk before touching current one (keeps 8 loads in flight)
        float4 n0 = __ldcs(in + (size_t)(t + 4) * F4);
        float4 n1 = __ldcs(in + (size_t)(t + 5) * F4);
        float4 n2 = __ldcs(in + (size_t)(t + 6) * F4);
        float4 n3 = __ldcs(in + (size_t)(t + 7) * F4);

        STEP_STORE(c0, t + 0);
        STEP_STORE(c1, t + 1);
        STEP_STORE(c2, t + 2);
        STEP_STORE(c3, t + 3);

        c0 = n0; c1 = n1; c2 = n2; c3 = n3;
    }

    // Epilogue: t = 124..127
    STEP_STORE(c0, T_STEPS - 4);
    STEP_STORE(c1, T_STEPS - 3);
    STEP_STORE(c2, T_STEPS - 2);
    STEP_STORE(c3, T_STEPS - 1);

    #undef STEP_STORE
}

extern "C" void kernel_launch(void* const* d_in, const int* in_sizes, int n_in,
                              void* d_out, int out_size) {
    const float4* x = (const float4*)d_in[0];
    float4* o = (float4*)d_out;
    const int total_threads = BATCH * F4;          // 131072
    spiking_layer_kernel<<<total_threads / 128, 128>>>(x, o);
}